// round 4
// baseline (speedup 1.0000x reference)
#include <cuda_runtime.h>
#include <math.h>

#define N_NODES 500000
#define N_EDGES 8000000
#define IN_DIM  128
#define H1      32
#define H2      16

#define SCAN_T   1024
#define SCAN_E   8
#define SCAN_BLK (SCAN_T * SCAN_E)                      // 8192
#define SCAN_NB  ((N_NODES + SCAN_BLK - 1) / SCAN_BLK)  // 62

// ---------------- constant-memory weights -----------------------------------
__constant__ float cW1[IN_DIM * H1];
__constant__ float cb1[H1];
__constant__ float cW2[H1 * H2];
__constant__ float cb2[H2];
__constant__ float cWfc[H2 * 2];
__constant__ float cbfc[2];

// ---------------- scratch (static device globals) ---------------------------
__device__ int      g_src[N_EDGES];
__device__ int      g_dst[N_EDGES];
__device__ int      g_col[N_EDGES];
__device__ unsigned g_deg[N_NODES];
__device__ unsigned g_rowptr[N_NODES + 1];
__device__ unsigned g_cursor[N_NODES];
__device__ unsigned long long g_state[SCAN_NB];  // decoupled-lookback states
__device__ float    g_dinv[N_NODES];
__device__ float    g_y1[(size_t)N_NODES * H1];
__device__ float    g_h1[(size_t)N_NODES * H1];
__device__ float    g_y2[(size_t)N_NODES * H2];
__device__ int      g_is64;

// ---------------- init: zero deg + scan state, detect edge dtype -------------
__global__ void k_init(const unsigned* __restrict__ ei32) {
    int i = blockIdx.x * blockDim.x + threadIdx.x;
    if (i < N_NODES) g_deg[i] = 0u;
    if (i < SCAN_NB) g_state[i] = 0ull;
    if (i == 0) {
        int is64 = 1;
        for (int e = 0; e < 256; e++)
            if (ei32[2 * e + 1] != 0u) { is64 = 0; break; }
        g_is64 = is64;
    }
}

// ---------------- convert to int32 + count in-degrees ------------------------
__global__ void k_convert(const void* __restrict__ ei) {
    int e = blockIdx.x * blockDim.x + threadIdx.x;
    if (e >= N_EDGES) return;
    int s, d;
    if (g_is64) {
        const long long* p = (const long long*)ei;
        s = (int)p[e];
        d = (int)p[(long long)N_EDGES + e];
    } else {
        const int* p = (const int*)ei;
        s = p[e];
        d = p[N_EDGES + e];
    }
    g_src[e] = s;
    g_dst[e] = d;
    atomicAdd(&g_deg[d], 1u);  // RED (no return value used)
}

// -------- single-kernel decoupled-lookback scan -> rowptr, cursor, dinv ------
__global__ void __launch_bounds__(SCAN_T, 1) k_scan() {
    __shared__ unsigned sh[SCAN_T];
    __shared__ unsigned s_excl;
    int tid = threadIdx.x, bid = blockIdx.x;
    int base = bid * SCAN_BLK + tid * SCAN_E;

    unsigned v[SCAN_E];
    unsigned s = 0;
#pragma unroll
    for (int j = 0; j < SCAN_E; j++) {
        int idx = base + j;
        v[j] = (idx < N_NODES) ? g_deg[idx] : 0u;
        s += v[j];
    }
    sh[tid] = s;
    __syncthreads();
    for (int off = 1; off < SCAN_T; off <<= 1) {
        unsigned t = (tid >= off) ? sh[tid - off] : 0u;
        __syncthreads();
        sh[tid] += t;
        __syncthreads();
    }
    unsigned run_local = sh[tid] - s;      // exclusive prefix within block
    unsigned total = sh[SCAN_T - 1];       // block aggregate

    // publish aggregate (or inclusive for block 0), then look back
    if (tid == 0) {
        if (bid == 0) {
            atomicExch(&g_state[0], (2ull << 32) | (unsigned long long)total);
            s_excl = 0u;
        } else {
            atomicExch(&g_state[bid], (1ull << 32) | (unsigned long long)total);
            unsigned excl = 0u;
            int p = bid - 1;
            while (true) {
                unsigned long long st;
                do { st = atomicAdd(&g_state[p], 0ull); } while ((st >> 32) == 0ull);
                excl += (unsigned)st;
                if ((st >> 32) == 2ull) break;
                p--;
            }
            s_excl = excl;
            atomicExch(&g_state[bid], (2ull << 32) | (unsigned long long)(excl + total));
        }
    }
    __syncthreads();

    unsigned run = run_local + s_excl;
#pragma unroll
    for (int j = 0; j < SCAN_E; j++) {
        int idx = base + j;
        if (idx < N_NODES) {
            g_rowptr[idx] = run;
            g_cursor[idx] = run;                         // fill cursor pre-seeded
            g_dinv[idx] = rsqrtf((float)(v[j] + 1u));    // +1 self-loop
        }
        run += v[j];
    }
    if (bid == 0 && tid == 0) g_rowptr[N_NODES] = (unsigned)N_EDGES;
}

// ---------------- layer 1 GEMM: y1 = (x @ W1) * dinv  (LAUNCH #4: profiled) --
__global__ void k_gemm1(const float* __restrict__ x) {
    int i = blockIdx.x * blockDim.x + threadIdx.x;
    if (i >= N_NODES) return;

    float acc[H1];
#pragma unroll
    for (int o = 0; o < H1; o++) acc[o] = 0.0f;

    const float4* xr = (const float4*)(x + (size_t)i * IN_DIM);
#pragma unroll 2
    for (int kk = 0; kk < IN_DIM / 4; kk++) {
        float4 v = __ldg(xr + kk);
        int k = kk * 4;
#pragma unroll
        for (int o = 0; o < H1; o++) {
            float a = acc[o];
            a = fmaf(v.x, cW1[(k + 0) * H1 + o], a);
            a = fmaf(v.y, cW1[(k + 1) * H1 + o], a);
            a = fmaf(v.z, cW1[(k + 2) * H1 + o], a);
            a = fmaf(v.w, cW1[(k + 3) * H1 + o], a);
            acc[o] = a;
        }
    }

    float di = g_dinv[i];
    float4* y = (float4*)(g_y1 + (size_t)i * H1);
#pragma unroll
    for (int q = 0; q < H1 / 4; q++) {
        float4 t;
        t.x = acc[q * 4 + 0] * di;
        t.y = acc[q * 4 + 1] * di;
        t.z = acc[q * 4 + 2] * di;
        t.w = acc[q * 4 + 3] * di;
        y[q] = t;
    }
}

// ---------------- CSR fill (cursor pre-seeded = rowptr) ----------------------
__global__ void k_fill() {
    int e = blockIdx.x * blockDim.x + threadIdx.x;
    if (e >= N_EDGES) return;
    int d = g_dst[e];
    unsigned p = atomicAdd(&g_cursor[d], 1u);
    g_col[p] = g_src[e];
}

// ---------------- gather L1 (warp/node, 4-wide ILP) + relu + bias -> h1 ------
__global__ void k_gather1() {
    int wid = (blockIdx.x * blockDim.x + threadIdx.x) >> 5;
    int lane = threadIdx.x & 31;
    if (wid >= N_NODES) return;
    int i = wid;

    unsigned beg = g_rowptr[i], end = g_rowptr[i + 1];
    float acc = g_y1[(size_t)i * H1 + lane];  // self-loop term (pre-scaled)

    unsigned j = beg;
    for (; j + 4 <= end; j += 4) {
        int s0 = g_col[j + 0];
        int s1 = g_col[j + 1];
        int s2 = g_col[j + 2];
        int s3 = g_col[j + 3];
        float a = g_y1[(size_t)s0 * H1 + lane];
        float b = g_y1[(size_t)s1 * H1 + lane];
        float c = g_y1[(size_t)s2 * H1 + lane];
        float d = g_y1[(size_t)s3 * H1 + lane];
        acc += a; acc += b; acc += c; acc += d;
    }
    for (; j < end; j++) acc += g_y1[(size_t)g_col[j] * H1 + lane];

    float di = g_dinv[i];
    g_h1[(size_t)i * H1 + lane] = fmaxf(fmaf(di, acc, cb1[lane]), 0.0f);
}

// ---------------- layer 2 GEMM: y2 = (h1 @ W2) * dinv ------------------------
__global__ void k_layer2() {
    int i = blockIdx.x * blockDim.x + threadIdx.x;
    if (i >= N_NODES) return;

    float h[H1];
    const float4* hp = (const float4*)(g_h1 + (size_t)i * H1);
#pragma unroll
    for (int q = 0; q < H1 / 4; q++) {
        float4 v = hp[q];
        h[q * 4 + 0] = v.x;
        h[q * 4 + 1] = v.y;
        h[q * 4 + 2] = v.z;
        h[q * 4 + 3] = v.w;
    }

    float acc[H2];
#pragma unroll
    for (int o = 0; o < H2; o++) acc[o] = 0.0f;
#pragma unroll 4
    for (int k = 0; k < H1; k++) {
        float hv = h[k];
#pragma unroll
        for (int o = 0; o < H2; o++)
            acc[o] = fmaf(hv, cW2[k * H2 + o], acc[o]);
    }

    float di = g_dinv[i];
    float4* y = (float4*)(g_y2 + (size_t)i * H2);
#pragma unroll
    for (int q = 0; q < H2 / 4; q++) {
        float4 t;
        t.x = acc[q * 4 + 0] * di;
        t.y = acc[q * 4 + 1] * di;
        t.z = acc[q * 4 + 2] * di;
        t.w = acc[q * 4 + 3] * di;
        y[q] = t;
    }
}

// ----- gather L2 (half-warp/node, 4-wide ILP) + relu + fc + log_softmax ------
__global__ void k_gather2_final(float* __restrict__ out) {
    int tid = blockIdx.x * blockDim.x + threadIdx.x;
    int hwid = tid >> 4;
    int o = threadIdx.x & 15;
    if (hwid >= N_NODES) return;
    int i = hwid;

    unsigned beg = g_rowptr[i], end = g_rowptr[i + 1];
    float acc = g_y2[(size_t)i * H2 + o];  // self-loop term

    unsigned j = beg;
    for (; j + 4 <= end; j += 4) {
        int s0 = g_col[j + 0];
        int s1 = g_col[j + 1];
        int s2 = g_col[j + 2];
        int s3 = g_col[j + 3];
        float a = g_y2[(size_t)s0 * H2 + o];
        float b = g_y2[(size_t)s1 * H2 + o];
        float c = g_y2[(size_t)s2 * H2 + o];
        float d = g_y2[(size_t)s3 * H2 + o];
        acc += a; acc += b; acc += c; acc += d;
    }
    for (; j < end; j++) acc += g_y2[(size_t)g_col[j] * H2 + o];

    float di = g_dinv[i];
    float h = fmaxf(fmaf(di, acc, cb2[o]), 0.0f);

    float p0 = h * cWfc[o * 2 + 0];
    float p1 = h * cWfc[o * 2 + 1];
#pragma unroll
    for (int off = 8; off >= 1; off >>= 1) {
        p0 += __shfl_xor_sync(0xffffffffu, p0, off, 16);
        p1 += __shfl_xor_sync(0xffffffffu, p1, off, 16);
    }
    if (o == 0) {
        float l0 = p0 + cbfc[0];
        float l1 = p1 + cbfc[1];
        float m = fmaxf(l0, l1);
        float lse = m + logf(expf(l0 - m) + expf(l1 - m));
        float2 r;
        r.x = l0 - lse;
        r.y = l1 - lse;
        ((float2*)out)[i] = r;
    }
}

// ---------------- launch -----------------------------------------------------
extern "C" void kernel_launch(void* const* d_in, const int* in_sizes, int n_in,
                              void* d_out, int out_size) {
    const float* x = (const float*)d_in[0];
    const void*  ei = d_in[1];

    cudaMemcpyToSymbolAsync(cW1,  d_in[2], IN_DIM * H1 * sizeof(float), 0, cudaMemcpyDeviceToDevice);
    cudaMemcpyToSymbolAsync(cb1,  d_in[3], H1 * sizeof(float),          0, cudaMemcpyDeviceToDevice);
    cudaMemcpyToSymbolAsync(cW2,  d_in[4], H1 * H2 * sizeof(float),     0, cudaMemcpyDeviceToDevice);
    cudaMemcpyToSymbolAsync(cb2,  d_in[5], H2 * sizeof(float),          0, cudaMemcpyDeviceToDevice);
    cudaMemcpyToSymbolAsync(cWfc, d_in[6], H2 * 2 * sizeof(float),      0, cudaMemcpyDeviceToDevice);
    cudaMemcpyToSymbolAsync(cbfc, d_in[7], 2 * sizeof(float),           0, cudaMemcpyDeviceToDevice);

    const int B = 256;
    const int GN = (N_NODES + B - 1) / B;
    const int GE = (N_EDGES + B - 1) / B;

    k_init<<<GN, B>>>((const unsigned*)ei);        // launch 1
    k_convert<<<GE, B>>>(ei);                      // launch 2
    k_scan<<<SCAN_NB, SCAN_T>>>();                 // launch 3
    k_gemm1<<<GN, B>>>(x);                         // launch 4  <- ncu profiles this
    k_fill<<<GE, B>>>();                           // launch 5
    k_gather1<<<(N_NODES + 7) / 8, B>>>();         // launch 6
    k_layer2<<<GN, B>>>();                         // launch 7
    k_gather2_final<<<(N_NODES + 15) / 16, B>>>((float*)d_out);  // launch 8
}

// round 5
// speedup vs baseline: 1.0249x; 1.0249x over previous
#include <cuda_runtime.h>
#include <math.h>

#define N_NODES 500000
#define N_EDGES 8000000
#define IN_DIM  128
#define H1      32
#define H2      16

#define SCAN_T   1024
#define SCAN_E   8
#define SCAN_BLK (SCAN_T * SCAN_E)                      // 8192
#define SCAN_NB  ((N_NODES + SCAN_BLK - 1) / SCAN_BLK)  // 62

// ---------------- constant-memory weights -----------------------------------
// W1 stored as packed 64-bit pairs: element [k*16+o] = (W1[k][2o], W1[k][2o+1])
__constant__ unsigned long long cW1p[IN_DIM * H1 / 2];
__constant__ float cb1[H1];
__constant__ float cW2[H1 * H2];
__constant__ float cb2[H2];
__constant__ float cWfc[H2 * 2];
__constant__ float cbfc[2];

// ---------------- scratch (static device globals) ---------------------------
__device__ int      g_col[N_EDGES];
__device__ unsigned g_deg[N_NODES];
__device__ unsigned g_rowptr[N_NODES + 1];
__device__ unsigned g_cursor[N_NODES];
__device__ unsigned long long g_state[SCAN_NB];
__device__ float    g_dinv[N_NODES];
__device__ float    g_y1[(size_t)N_NODES * H1];
__device__ float    g_h1[(size_t)N_NODES * H1];
__device__ float    g_y2[(size_t)N_NODES * H2];
__device__ int      g_is64;

// ---------------- init: zero deg + scan state, detect edge dtype -------------
__global__ void k_init(const unsigned* __restrict__ ei32) {
    int i = blockIdx.x * blockDim.x + threadIdx.x;
    if (i < N_NODES) g_deg[i] = 0u;
    if (i < SCAN_NB) g_state[i] = 0ull;
    if (i == 0) {
        int is64 = 1;
        for (int e = 0; e < 256; e++)
            if (ei32[2 * e + 1] != 0u) { is64 = 0; break; }
        g_is64 = is64;
    }
}

// ---------------- count in-degrees (dst half only) ---------------------------
__global__ void k_count(const void* __restrict__ ei) {
    int e = blockIdx.x * blockDim.x + threadIdx.x;
    if (e >= N_EDGES) return;
    int d;
    if (g_is64) d = (int)((const long long*)ei)[(long long)N_EDGES + e];
    else        d = ((const int*)ei)[N_EDGES + e];
    atomicAdd(&g_deg[d], 1u);
}

// -------- single-kernel decoupled-lookback scan -> rowptr, cursor, dinv ------
__global__ void __launch_bounds__(SCAN_T, 1) k_scan() {
    __shared__ unsigned sh[SCAN_T];
    __shared__ unsigned s_excl;
    int tid = threadIdx.x, bid = blockIdx.x;
    int base = bid * SCAN_BLK + tid * SCAN_E;

    unsigned v[SCAN_E];
    unsigned s = 0;
#pragma unroll
    for (int j = 0; j < SCAN_E; j++) {
        int idx = base + j;
        v[j] = (idx < N_NODES) ? g_deg[idx] : 0u;
        s += v[j];
    }
    sh[tid] = s;
    __syncthreads();
    for (int off = 1; off < SCAN_T; off <<= 1) {
        unsigned t = (tid >= off) ? sh[tid - off] : 0u;
        __syncthreads();
        sh[tid] += t;
        __syncthreads();
    }
    unsigned run_local = sh[tid] - s;
    unsigned total = sh[SCAN_T - 1];

    if (tid == 0) {
        if (bid == 0) {
            atomicExch(&g_state[0], (2ull << 32) | (unsigned long long)total);
            s_excl = 0u;
        } else {
            atomicExch(&g_state[bid], (1ull << 32) | (unsigned long long)total);
            unsigned excl = 0u;
            int p = bid - 1;
            while (true) {
                unsigned long long st;
                do { st = atomicAdd(&g_state[p], 0ull); } while ((st >> 32) == 0ull);
                excl += (unsigned)st;
                if ((st >> 32) == 2ull) break;
                p--;
            }
            s_excl = excl;
            atomicExch(&g_state[bid], (2ull << 32) | (unsigned long long)(excl + total));
        }
    }
    __syncthreads();

    unsigned run = run_local + s_excl;
#pragma unroll
    for (int j = 0; j < SCAN_E; j++) {
        int idx = base + j;
        if (idx < N_NODES) {
            g_rowptr[idx] = run;
            g_cursor[idx] = run;
            g_dinv[idx] = rsqrtf((float)(v[j] + 1u));
        }
        run += v[j];
    }
    if (bid == 0 && tid == 0) g_rowptr[N_NODES] = (unsigned)N_EDGES;
}

// ---------------- CSR fill (reads edge_index directly; LAUNCH 4: profiled) ---
__global__ void k_fill(const void* __restrict__ ei) {
    int e = blockIdx.x * blockDim.x + threadIdx.x;
    if (e >= N_EDGES) return;
    int s, d;
    if (g_is64) {
        const long long* p = (const long long*)ei;
        s = (int)p[e];
        d = (int)p[(long long)N_EDGES + e];
    } else {
        const int* p = (const int*)ei;
        s = p[e];
        d = p[N_EDGES + e];
    }
    unsigned pos = atomicAdd(&g_cursor[d], 1u);
    g_col[pos] = s;
}

// ---------------- layer 1 GEMM (packed f32x2): y1 = (x @ W1) * dinv ----------
__global__ void k_gemm1(const float* __restrict__ x) {
    int i = blockIdx.x * blockDim.x + threadIdx.x;
    if (i >= N_NODES) return;

    unsigned long long acc[H1 / 2];
#pragma unroll
    for (int o = 0; o < H1 / 2; o++) acc[o] = 0ull;

    const float4* xr = (const float4*)(x + (size_t)i * IN_DIM);
#pragma unroll 2
    for (int kk = 0; kk < IN_DIM / 4; kk++) {
        float4 v = __ldg(xr + kk);
        float vv[4] = {v.x, v.y, v.z, v.w};
        int k = kk * 4;
#pragma unroll
        for (int t = 0; t < 4; t++) {
            unsigned long long xx;
            asm("mov.b64 %0, {%1, %1};" : "=l"(xx) : "f"(vv[t]));
            const unsigned long long* w = &cW1p[(k + t) * (H1 / 2)];
#pragma unroll
            for (int o = 0; o < H1 / 2; o++) {
                asm("fma.rn.f32x2 %0, %1, %2, %0;"
                    : "+l"(acc[o]) : "l"(xx), "l"(w[o]));
            }
        }
    }

    float di = g_dinv[i];
    float4* y = (float4*)(g_y1 + (size_t)i * H1);
#pragma unroll
    for (int q = 0; q < H1 / 4; q++) {
        float a0, a1, a2, a3;
        asm("mov.b64 {%0, %1}, %2;" : "=f"(a0), "=f"(a1) : "l"(acc[q * 2 + 0]));
        asm("mov.b64 {%0, %1}, %2;" : "=f"(a2), "=f"(a3) : "l"(acc[q * 2 + 1]));
        float4 t;
        t.x = a0 * di; t.y = a1 * di; t.z = a2 * di; t.w = a3 * di;
        y[q] = t;
    }
}

// ---------------- gather L1 (warp/node, 4-wide ILP) + relu + bias -> h1 ------
__global__ void k_gather1() {
    int wid = (blockIdx.x * blockDim.x + threadIdx.x) >> 5;
    int lane = threadIdx.x & 31;
    if (wid >= N_NODES) return;
    int i = wid;

    unsigned beg = g_rowptr[i], end = g_rowptr[i + 1];
    float acc = g_y1[(size_t)i * H1 + lane];

    unsigned j = beg;
    for (; j + 4 <= end; j += 4) {
        int s0 = g_col[j + 0];
        int s1 = g_col[j + 1];
        int s2 = g_col[j + 2];
        int s3 = g_col[j + 3];
        float a = g_y1[(size_t)s0 * H1 + lane];
        float b = g_y1[(size_t)s1 * H1 + lane];
        float c = g_y1[(size_t)s2 * H1 + lane];
        float d = g_y1[(size_t)s3 * H1 + lane];
        acc += a; acc += b; acc += c; acc += d;
    }
    for (; j < end; j++) acc += g_y1[(size_t)g_col[j] * H1 + lane];

    float di = g_dinv[i];
    g_h1[(size_t)i * H1 + lane] = fmaxf(fmaf(di, acc, cb1[lane]), 0.0f);
}

// ---------------- layer 2 GEMM: y2 = (h1 @ W2) * dinv ------------------------
__global__ void k_layer2() {
    int i = blockIdx.x * blockDim.x + threadIdx.x;
    if (i >= N_NODES) return;

    float h[H1];
    const float4* hp = (const float4*)(g_h1 + (size_t)i * H1);
#pragma unroll
    for (int q = 0; q < H1 / 4; q++) {
        float4 v = hp[q];
        h[q * 4 + 0] = v.x;
        h[q * 4 + 1] = v.y;
        h[q * 4 + 2] = v.z;
        h[q * 4 + 3] = v.w;
    }

    float acc[H2];
#pragma unroll
    for (int o = 0; o < H2; o++) acc[o] = 0.0f;
#pragma unroll 4
    for (int k = 0; k < H1; k++) {
        float hv = h[k];
#pragma unroll
        for (int o = 0; o < H2; o++)
            acc[o] = fmaf(hv, cW2[k * H2 + o], acc[o]);
    }

    float di = g_dinv[i];
    float4* y = (float4*)(g_y2 + (size_t)i * H2);
#pragma unroll
    for (int q = 0; q < H2 / 4; q++) {
        float4 t;
        t.x = acc[q * 4 + 0] * di;
        t.y = acc[q * 4 + 1] * di;
        t.z = acc[q * 4 + 2] * di;
        t.w = acc[q * 4 + 3] * di;
        y[q] = t;
    }
}

// ----- gather L2 (half-warp/node, 4-wide ILP) + relu + fc + log_softmax ------
__global__ void k_gather2_final(float* __restrict__ out) {
    int tid = blockIdx.x * blockDim.x + threadIdx.x;
    int hwid = tid >> 4;
    int o = threadIdx.x & 15;
    if (hwid >= N_NODES) return;
    int i = hwid;

    unsigned beg = g_rowptr[i], end = g_rowptr[i + 1];
    float acc = g_y2[(size_t)i * H2 + o];

    unsigned j = beg;
    for (; j + 4 <= end; j += 4) {
        int s0 = g_col[j + 0];
        int s1 = g_col[j + 1];
        int s2 = g_col[j + 2];
        int s3 = g_col[j + 3];
        float a = g_y2[(size_t)s0 * H2 + o];
        float b = g_y2[(size_t)s1 * H2 + o];
        float c = g_y2[(size_t)s2 * H2 + o];
        float d = g_y2[(size_t)s3 * H2 + o];
        acc += a; acc += b; acc += c; acc += d;
    }
    for (; j < end; j++) acc += g_y2[(size_t)g_col[j] * H2 + o];

    float di = g_dinv[i];
    float h = fmaxf(fmaf(di, acc, cb2[o]), 0.0f);

    float p0 = h * cWfc[o * 2 + 0];
    float p1 = h * cWfc[o * 2 + 1];
#pragma unroll
    for (int off = 8; off >= 1; off >>= 1) {
        p0 += __shfl_xor_sync(0xffffffffu, p0, off, 16);
        p1 += __shfl_xor_sync(0xffffffffu, p1, off, 16);
    }
    if (o == 0) {
        float l0 = p0 + cbfc[0];
        float l1 = p1 + cbfc[1];
        float m = fmaxf(l0, l1);
        float lse = m + logf(expf(l0 - m) + expf(l1 - m));
        float2 r;
        r.x = l0 - lse;
        r.y = l1 - lse;
        ((float2*)out)[i] = r;
    }
}

// ---------------- launch -----------------------------------------------------
extern "C" void kernel_launch(void* const* d_in, const int* in_sizes, int n_in,
                              void* d_out, int out_size) {
    const float* x = (const float*)d_in[0];
    const void*  ei = d_in[1];

    cudaMemcpyToSymbolAsync(cW1p, d_in[2], IN_DIM * H1 * sizeof(float), 0, cudaMemcpyDeviceToDevice);
    cudaMemcpyToSymbolAsync(cb1,  d_in[3], H1 * sizeof(float),          0, cudaMemcpyDeviceToDevice);
    cudaMemcpyToSymbolAsync(cW2,  d_in[4], H1 * H2 * sizeof(float),     0, cudaMemcpyDeviceToDevice);
    cudaMemcpyToSymbolAsync(cb2,  d_in[5], H2 * sizeof(float),          0, cudaMemcpyDeviceToDevice);
    cudaMemcpyToSymbolAsync(cWfc, d_in[6], H2 * 2 * sizeof(float),      0, cudaMemcpyDeviceToDevice);
    cudaMemcpyToSymbolAsync(cbfc, d_in[7], 2 * sizeof(float),           0, cudaMemcpyDeviceToDevice);

    const int B = 256;
    const int GN = (N_NODES + B - 1) / B;
    const int GE = (N_EDGES + B - 1) / B;

    k_init<<<GN, B>>>((const unsigned*)ei);        // 1
    k_count<<<GE, B>>>(ei);                        // 2
    k_scan<<<SCAN_NB, SCAN_T>>>();                 // 3
    k_fill<<<GE, B>>>(ei);                         // 4  <- ncu profiles this
    k_gemm1<<<GN, B>>>(x);                         // 5
    k_gather1<<<(N_NODES + 7) / 8, B>>>();         // 6
    k_layer2<<<GN, B>>>();                         // 7
    k_gather2_final<<<(N_NODES + 15) / 16, B>>>((float*)d_out);  // 8
}